// round 1
// baseline (speedup 1.0000x reference)
#include <cuda_runtime.h>
#include <math.h>

// ---------------- problem constants ----------------
namespace {
constexpr int cB  = 2;
constexpr int cS  = 2048;
constexpr int cH  = 3072;
constexpr int cNH = 16;
constexpr int cHD = 256;
constexpr int cQSZ  = cNH * cHD;            // 4096
constexpr int cKVSZ = cQSZ;                 // 4096 (NKV == NH)
constexpr int cQKV  = cQSZ + 2 * cKVSZ;     // 12288
constexpr int cM    = cB * cS;              // 4096 rows
}

// ---------------- scratch (no cudaMalloc allowed) ----------------
__device__ float g_qkv[(size_t)cM * cQKV];   // 201 MB
__device__ float g_attn[(size_t)cM * cQSZ];  // 67 MB

// ---------------- SGEMM: C[M,N] = A[M,K] * B[K,N], fp32 ----------------
// 128x128 block tile, BK=16, 256 threads, 8x8 per thread.
// Assumes M%128==0, N%128==0, K%16==0 (true for all our shapes).
__global__ __launch_bounds__(256) void sgemm_kernel(
    const float* __restrict__ A, const float* __restrict__ Bm,
    float* __restrict__ C, int M, int N, int K) {
  constexpr int BM = 128, BN = 128, BK = 16, TM = 8, TN = 8;
  __shared__ float As[BK][BM];
  __shared__ float Bs[BK][BN];

  const int tid = threadIdx.x;
  const int tx = tid & 15, ty = tid >> 4;

  const float* Ab = A + (size_t)blockIdx.y * BM * K;
  const float* Bb = Bm + (size_t)blockIdx.x * BN;

  float acc[TM][TN] = {};

  for (int k0 = 0; k0 < K; k0 += BK) {
    // load A tile (128x16) -> As[k][row] (transposed)
    #pragma unroll
    for (int i = 0; i < 2; i++) {
      int idx = tid + i * 256;          // 0..511 float4 slots
      int row = idx >> 2;               // 0..127
      int kq  = idx & 3;                // 0..3
      float4 v = *(const float4*)(Ab + (size_t)row * K + k0 + kq * 4);
      As[kq * 4 + 0][row] = v.x;
      As[kq * 4 + 1][row] = v.y;
      As[kq * 4 + 2][row] = v.z;
      As[kq * 4 + 3][row] = v.w;
    }
    // load B tile (16x128) -> Bs[row][col]
    #pragma unroll
    for (int i = 0; i < 2; i++) {
      int idx = tid + i * 256;
      int row = idx >> 5;               // 0..15
      int cq  = idx & 31;               // 0..31
      *(float4*)(&Bs[row][cq * 4]) =
          *(const float4*)(Bb + (size_t)(k0 + row) * N + cq * 4);
    }
    __syncthreads();

    #pragma unroll
    for (int k = 0; k < BK; k++) {
      float4 a0 = *(const float4*)(&As[k][ty * TM]);
      float4 a1 = *(const float4*)(&As[k][ty * TM + 4]);
      float4 b0 = *(const float4*)(&Bs[k][tx * TN]);
      float4 b1 = *(const float4*)(&Bs[k][tx * TN + 4]);
      float a[TM] = {a0.x, a0.y, a0.z, a0.w, a1.x, a1.y, a1.z, a1.w};
      float b[TN] = {b0.x, b0.y, b0.z, b0.w, b1.x, b1.y, b1.z, b1.w};
      #pragma unroll
      for (int i = 0; i < TM; i++)
        #pragma unroll
        for (int j = 0; j < TN; j++)
          acc[i][j] += a[i] * b[j];
    }
    __syncthreads();
  }

  float* Cb = C + (size_t)(blockIdx.y * BM) * N + blockIdx.x * BN;
  #pragma unroll
  for (int i = 0; i < TM; i++) {
    #pragma unroll
    for (int j = 0; j < TN; j += 4) {
      float4 v = make_float4(acc[i][j], acc[i][j + 1], acc[i][j + 2], acc[i][j + 3]);
      *(float4*)(Cb + (size_t)(ty * TM + i) * N + tx * TN + j) = v;
    }
  }
}

// ---------------- RoPE (neox) applied in place to q and k of g_qkv ----------------
// q heads (0..15) and k heads (16..31) are contiguous in the 12288-wide row.
__global__ __launch_bounds__(256) void rope_kernel(const int* __restrict__ pos) {
  int idx = blockIdx.x * 256 + threadIdx.x;      // total cM*32*128 = 16.7M
  int i   = idx & 127;                           // rotary pair index (half=128)
  int hh  = (idx >> 7) & 31;                     // head 0..31 (q then k)
  int row = idx >> 12;                           // token row 0..4095
  int p = pos[row];
  // angle computed in double: pos*inv_freq can reach ~2047 rad; fp32 inv_freq
  // error * pos would cost ~2e-4 rad. ln(10000) = 9.210340371976184
  double inv = exp(((double)(-2.0 * i) / 256.0) * 9.210340371976184);
  double ang = (double)p * inv;
  double sd, cd;
  sincos(ang, &sd, &cd);
  float c = (float)cd, s = (float)sd;
  float* base = g_qkv + (size_t)row * cQKV + hh * cHD;
  float x1 = base[i], x2 = base[i + 128];
  base[i]       = x1 * c - x2 * s;
  base[i + 128] = x2 * c + x1 * s;
}

// ---------------- causal flash attention, fp32 ----------------
// One block handles 64 queries of one (b,h). Q/K/V tiles fully in smem.
// 256 threads: (ty,tx) 16x16. Thread owns query rows ty*4..+3 and output
// columns {tx + 16*i2}. Scores tile 64x64 staged in smem for online softmax.
constexpr int BQ = 64, BKV = 64;
constexpr int QST = 257;   // Q/K row stride (odd -> conflict-free column walks)
constexpr int VST = 260;   // V row stride (16B-aligned rows for float4)
constexpr int SST = 65;    // scores row stride
constexpr int FLASH_SMEM =
    (BQ * QST + BKV * QST + BKV * VST + BQ * SST + 3 * BQ) * 4;  // 215552 B

__global__ __launch_bounds__(256) void flash_kernel() {
  extern __shared__ float smf[];
  float* Qs  = smf;
  float* Ks  = Qs + BQ * QST;
  float* Vs  = Ks + BKV * QST;
  float* Ss  = Vs + BKV * VST;
  float* m_s = Ss + BQ * SST;
  float* l_s = m_s + BQ;
  float* f_s = l_s + BQ;

  const int qtile = gridDim.x - 1 - blockIdx.x;  // heavy tiles scheduled first
  const int bh = blockIdx.y;
  const int b = bh / cNH, h = bh % cNH;
  const int tid = threadIdx.x;
  const int tx = tid & 15, ty = tid >> 4;
  const int r0 = ty * 4;
  const int c0 = tx * 4;
  const float scale = 0.0625f;  // 256^-0.5

  // load Q tile [64 x 256]
  const float* qb = g_qkv + (size_t)(b * cS + qtile * BQ) * cQKV + h * cHD;
  #pragma unroll
  for (int l = 0; l < 16; l++) {
    int idx = l * 256 + tid;
    int r = idx >> 6, d4 = idx & 63;
    float4 v = *(const float4*)(qb + (size_t)r * cQKV + d4 * 4);
    float* dst = Qs + r * QST + d4 * 4;
    dst[0] = v.x; dst[1] = v.y; dst[2] = v.z; dst[3] = v.w;
  }
  if (tid < BQ) { m_s[tid] = -1e30f; l_s[tid] = 0.0f; }

  float O[4][16];
  #pragma unroll
  for (int i = 0; i < 4; i++)
    #pragma unroll
    for (int j = 0; j < 16; j++) O[i][j] = 0.0f;

  for (int jt = 0; jt <= qtile; jt++) {
    __syncthreads();  // Q ready / previous iteration's PV reads done

    // load K,V tiles [64 x 256]
    const float* kb = g_qkv + (size_t)(b * cS + jt * BKV) * cQKV + cQSZ + h * cHD;
    const float* vb = kb + cKVSZ;
    #pragma unroll
    for (int l = 0; l < 16; l++) {
      int idx = l * 256 + tid;
      int r = idx >> 6, d4 = idx & 63;
      float4 v = *(const float4*)(kb + (size_t)r * cQKV + d4 * 4);
      float* dst = Ks + r * QST + d4 * 4;
      dst[0] = v.x; dst[1] = v.y; dst[2] = v.z; dst[3] = v.w;
      float4 w = *(const float4*)(vb + (size_t)r * cQKV + d4 * 4);
      *(float4*)(Vs + r * VST + d4 * 4) = w;
    }
    __syncthreads();

    // scores: sc[4][4] = Q[r0..r0+3] . K[c0..c0+3]
    float sc[4][4] = {};
    #pragma unroll 4
    for (int d = 0; d < cHD; d++) {
      float a0 = Qs[(r0 + 0) * QST + d];
      float a1 = Qs[(r0 + 1) * QST + d];
      float a2 = Qs[(r0 + 2) * QST + d];
      float a3 = Qs[(r0 + 3) * QST + d];
      float k0 = Ks[(c0 + 0) * QST + d];
      float k1 = Ks[(c0 + 1) * QST + d];
      float k2 = Ks[(c0 + 2) * QST + d];
      float k3 = Ks[(c0 + 3) * QST + d];
      sc[0][0] += a0 * k0; sc[0][1] += a0 * k1; sc[0][2] += a0 * k2; sc[0][3] += a0 * k3;
      sc[1][0] += a1 * k0; sc[1][1] += a1 * k1; sc[1][2] += a1 * k2; sc[1][3] += a1 * k3;
      sc[2][0] += a2 * k0; sc[2][1] += a2 * k1; sc[2][2] += a2 * k2; sc[2][3] += a2 * k3;
      sc[3][0] += a3 * k0; sc[3][1] += a3 * k1; sc[3][2] += a3 * k2; sc[3][3] += a3 * k3;
    }
    #pragma unroll
    for (int i = 0; i < 4; i++) {
      int qg = qtile * BQ + r0 + i;
      #pragma unroll
      for (int j = 0; j < 4; j++) {
        int kg = jt * BKV + c0 + j;
        Ss[(r0 + i) * SST + c0 + j] = (kg <= qg) ? sc[i][j] * scale : -1e30f;
      }
    }
    __syncthreads();

    // online softmax: 4 lanes per row
    {
      int row = tid >> 2, qq = tid & 3;
      float* srow = Ss + row * SST + qq * 16;
      float lm = -1e30f;
      #pragma unroll
      for (int j = 0; j < 16; j++) lm = fmaxf(lm, srow[j]);
      lm = fmaxf(lm, __shfl_xor_sync(0xffffffffu, lm, 1));
      lm = fmaxf(lm, __shfl_xor_sync(0xffffffffu, lm, 2));
      float mold = m_s[row];
      float mnew = fmaxf(mold, lm);
      float sum = 0.0f;
      #pragma unroll
      for (int j = 0; j < 16; j++) {
        float p = expf(srow[j] - mnew);
        srow[j] = p;
        sum += p;
      }
      sum += __shfl_xor_sync(0xffffffffu, sum, 1);
      sum += __shfl_xor_sync(0xffffffffu, sum, 2);
      if (qq == 0) {
        float f = expf(mold - mnew);
        f_s[row] = f;
        m_s[row] = mnew;
        l_s[row] = l_s[row] * f + sum;
      }
    }
    __syncthreads();

    // rescale O, then O += P * V
    float f0 = f_s[r0], f1 = f_s[r0 + 1], f2 = f_s[r0 + 2], f3 = f_s[r0 + 3];
    #pragma unroll
    for (int i2 = 0; i2 < 16; i2++) {
      O[0][i2] *= f0; O[1][i2] *= f1; O[2][i2] *= f2; O[3][i2] *= f3;
    }
    for (int kk = 0; kk < BKV; kk++) {
      float p0 = Ss[(r0 + 0) * SST + kk];
      float p1 = Ss[(r0 + 1) * SST + kk];
      float p2 = Ss[(r0 + 2) * SST + kk];
      float p3 = Ss[(r0 + 3) * SST + kk];
      const float* vr = Vs + kk * VST + tx;
      #pragma unroll
      for (int i2 = 0; i2 < 16; i2++) {
        float v = vr[i2 * 16];
        O[0][i2] += p0 * v;
        O[1][i2] += p1 * v;
        O[2][i2] += p2 * v;
        O[3][i2] += p3 * v;
      }
    }
  }

  // epilogue: O /= l, write to g_attn[(b,q), h*256 + c]
  float* ob = g_attn + (size_t)(b * cS + qtile * BQ) * cQSZ + h * cHD;
  #pragma unroll
  for (int i = 0; i < 4; i++) {
    float rl = 1.0f / l_s[r0 + i];
    #pragma unroll
    for (int i2 = 0; i2 < 16; i2++) {
      ob[(size_t)(r0 + i) * cQSZ + tx + 16 * i2] = O[i][i2] * rl;
    }
  }
}

// ---------------- launch ----------------
extern "C" void kernel_launch(void* const* d_in, const int* in_sizes, int n_in,
                              void* d_out, int out_size) {
  (void)in_sizes; (void)n_in; (void)out_size;
  const float* hidden = (const float*)d_in[0];
  const int*   pos    = (const int*)d_in[1];
  const float* Wqkv   = (const float*)d_in[2];
  const float* Wo     = (const float*)d_in[3];
  float* out = (float*)d_out;

  float *qkv_p = nullptr, *attn_p = nullptr;
  cudaGetSymbolAddress((void**)&qkv_p, g_qkv);
  cudaGetSymbolAddress((void**)&attn_p, g_attn);

  cudaFuncSetAttribute(flash_kernel,
                       cudaFuncAttributeMaxDynamicSharedMemorySize, FLASH_SMEM);

  // 1) QKV projection: [4096,3072] x [3072,12288]
  sgemm_kernel<<<dim3(cQKV / 128, cM / 128), 256>>>(hidden, Wqkv, qkv_p,
                                                    cM, cQKV, cH);
  // 2) RoPE on q and k
  rope_kernel<<<(cM * 32 * 128) / 256, 256>>>(pos);
  // 3) causal flash attention
  flash_kernel<<<dim3(cS / BQ, cB * cNH), 256, FLASH_SMEM>>>();
  // 4) output projection: [4096,4096] x [4096,3072]
  sgemm_kernel<<<dim3(cH / 128, cM / 128), 256>>>(attn_p, Wo, out,
                                                  cM, cH, cQSZ);
}

// round 3
// speedup vs baseline: 1.7136x; 1.7136x over previous
#include <cuda_runtime.h>
#include <cuda_bf16.h>
#include <math.h>
#include <stdint.h>

// ---------------- problem constants ----------------
namespace {
constexpr int cB  = 2;
constexpr int cS  = 2048;
constexpr int cH  = 3072;
constexpr int cNH = 16;
constexpr int cHD = 256;
constexpr int cQSZ  = cNH * cHD;            // 4096
constexpr int cKVSZ = cQSZ;                 // 4096 (NKV == NH)
constexpr int cQKV  = cQSZ + 2 * cKVSZ;     // 12288
constexpr int cM    = cB * cS;              // 4096 rows
}

// ---------------- scratch (no cudaMalloc allowed) ----------------
__device__ float g_qkv[(size_t)cM * cQKV];            // fp32 qkv
__device__ float g_attn[(size_t)cM * cQSZ];           // fp32 attn out
__device__ __nv_bfloat16 g_hid_h[(size_t)cM * cH];
__device__ __nv_bfloat16 g_hid_l[(size_t)cM * cH];
__device__ __nv_bfloat16 g_w1_h[(size_t)cQKV * cH];   // Wqkv^T [12288,3072]
__device__ __nv_bfloat16 g_w1_l[(size_t)cQKV * cH];
__device__ __nv_bfloat16 g_at_h[(size_t)cM * cQSZ];
__device__ __nv_bfloat16 g_at_l[(size_t)cM * cQSZ];
__device__ __nv_bfloat16 g_w2_h[(size_t)cH * cQSZ];   // Wo^T [3072,4096]
__device__ __nv_bfloat16 g_w2_l[(size_t)cH * cQSZ];

// ---------------- helpers (base ISA only: compute_103-safe) ----------------
__device__ __forceinline__ uint32_t smem_u32(const void* p) {
  uint32_t a;
  asm("{ .reg .u64 t; cvta.to.shared.u64 t, %1; cvt.u32.u64 %0, t; }"
      : "=r"(a) : "l"(p));
  return a;
}
#define CP_ASYNC16(dst, src) \
  asm volatile("cp.async.cg.shared.global [%0], [%1], 16;" :: "r"(dst), "l"(src))
#define CP_COMMIT() asm volatile("cp.async.commit_group;" ::: "memory")
#define CP_WAIT(n)  asm volatile("cp.async.wait_group %0;" :: "n"(n) : "memory")
#define LDSM4(r0, r1, r2, r3, addr) \
  asm volatile("ldmatrix.sync.aligned.m8n8.x4.shared.b16 {%0,%1,%2,%3}, [%4];" \
               : "=r"(r0), "=r"(r1), "=r"(r2), "=r"(r3) : "r"(addr))

__device__ __forceinline__ void mma16816(float* d, const uint32_t* a,
                                         const uint32_t* b) {
  asm volatile(
      "mma.sync.aligned.m16n8k16.row.col.f32.bf16.bf16.f32 "
      "{%0,%1,%2,%3}, {%4,%5,%6,%7}, {%8,%9}, {%0,%1,%2,%3};"
      : "+f"(d[0]), "+f"(d[1]), "+f"(d[2]), "+f"(d[3])
      : "r"(a[0]), "r"(a[1]), "r"(a[2]), "r"(a[3]), "r"(b[0]), "r"(b[1]));
}

// ---------------- split fp32 -> bf16 hi/lo ----------------
__global__ __launch_bounds__(256) void split_kernel(
    const float* __restrict__ x, __nv_bfloat16* __restrict__ h,
    __nv_bfloat16* __restrict__ l, int n4) {
  int i = blockIdx.x * 256 + threadIdx.x;
  if (i >= n4) return;
  float4 v = ((const float4*)x)[i];
  float vv[4] = {v.x, v.y, v.z, v.w};
  __nv_bfloat16 hh[4], ll[4];
  #pragma unroll
  for (int q = 0; q < 4; q++) {
    hh[q] = __float2bfloat16(vv[q]);
    ll[q] = __float2bfloat16(vv[q] - __bfloat162float(hh[q]));
  }
  ((__nv_bfloat162*)h)[2 * i]     = __nv_bfloat162(hh[0], hh[1]);
  ((__nv_bfloat162*)h)[2 * i + 1] = __nv_bfloat162(hh[2], hh[3]);
  ((__nv_bfloat162*)l)[2 * i]     = __nv_bfloat162(ll[0], ll[1]);
  ((__nv_bfloat162*)l)[2 * i + 1] = __nv_bfloat162(ll[2], ll[3]);
}

// ---------------- transpose + split: W[K,N] fp32 -> Wt[N,K] bf16 hi/lo ----------------
__global__ __launch_bounds__(256) void tsplit_kernel(
    const float* __restrict__ W, __nv_bfloat16* __restrict__ Th,
    __nv_bfloat16* __restrict__ Tl, int K, int N) {
  __shared__ float sm[32][33];
  int n0 = blockIdx.x * 32, k0 = blockIdx.y * 32;
  int tx = threadIdx.x & 31, ty = threadIdx.x >> 5;  // ty 0..7
  #pragma unroll
  for (int q = 0; q < 4; q++)
    sm[ty + 8 * q][tx] = W[(size_t)(k0 + ty + 8 * q) * N + n0 + tx];
  __syncthreads();
  #pragma unroll
  for (int q = 0; q < 4; q++) {
    float x = sm[tx][ty + 8 * q];  // W[k0+tx][n0+ty+8q]
    __nv_bfloat16 h = __float2bfloat16(x);
    float lo = x - __bfloat162float(h);
    size_t o = (size_t)(n0 + ty + 8 * q) * K + k0 + tx;
    Th[o] = h;
    Tl[o] = __float2bfloat16(lo);
  }
}

// ---------------- HMMA GEMM: C[M,N] = A[M,K] * Bt[N,K]^T, hi/lo split ----------------
// 128x128 CTA tile, BK=32, 8 warps (2x4) each 64x32, mma.m16n8k16 bf16.
constexpr int BM = 128, BN = 128, BKt = 32;
constexpr int AST = 40;                 // smem row stride in bf16 (80 B)
constexpr int PARTE = 128 * AST;        // bf16 elems per part (A_h/A_l/B_h/B_l)
constexpr int BUFE  = 4 * PARTE;        // bf16 elems per buffer
constexpr int HG_SMEM = 2 * BUFE * 2;   // bytes = 81920

__global__ __launch_bounds__(256, 2) void gemm_hmma(
    const __nv_bfloat16* __restrict__ Ah, const __nv_bfloat16* __restrict__ Al,
    const __nv_bfloat16* __restrict__ Bh, const __nv_bfloat16* __restrict__ Bl,
    float* __restrict__ C, int M, int N, int K) {
  extern __shared__ __nv_bfloat16 smb[];
  const uint32_t sbase = smem_u32(smb);
  const int tid = threadIdx.x, lane = tid & 31, wid = tid >> 5;
  const int m0 = blockIdx.y * BM, n0 = blockIdx.x * BN;
  const int wm = (wid & 1) * 64, wn = (wid >> 1) * 32;

  float acc[4][4][4];
  #pragma unroll
  for (int i = 0; i < 4; i++)
    #pragma unroll
    for (int j = 0; j < 4; j++)
      #pragma unroll
      for (int q = 0; q < 4; q++) acc[i][j][q] = 0.0f;

  const int T = K / BKt;

  // per-thread load slots: 2 chunks of 16B per part
  int ldr[2], ldc[2];
  #pragma unroll
  for (int i = 0; i < 2; i++) {
    int idx = tid + i * 256;
    ldr[i] = idx >> 2;
    ldc[i] = idx & 3;
  }

  #define ISSUE(t)                                                          \
    do {                                                                    \
      int k0_ = (t) * BKt;                                                  \
      uint32_t db_ = sbase + ((t) & 1) * (BUFE * 2);                        \
      _Pragma("unroll")                                                     \
      for (int i_ = 0; i_ < 2; i_++) {                                      \
        int r_ = ldr[i_], c_ = ldc[i_];                                     \
        size_t ao_ = (size_t)(m0 + r_) * K + k0_ + c_ * 8;                  \
        size_t bo_ = (size_t)(n0 + r_) * K + k0_ + c_ * 8;                  \
        uint32_t d_ = db_ + (r_ * AST + c_ * 8) * 2;                        \
        CP_ASYNC16(d_, Ah + ao_);                                           \
        CP_ASYNC16(d_ + PARTE * 2, Al + ao_);                               \
        CP_ASYNC16(d_ + 2 * PARTE * 2, Bh + bo_);                           \
        CP_ASYNC16(d_ + 3 * PARTE * 2, Bl + bo_);                           \
      }                                                                     \
    } while (0)

  ISSUE(0);
  CP_COMMIT();

  for (int t = 0; t < T; t++) {
    if (t + 1 < T) {
      ISSUE(t + 1);
      CP_COMMIT();
      CP_WAIT(1);
    } else {
      CP_WAIT(0);
    }
    __syncthreads();

    uint32_t base = sbase + (t & 1) * (BUFE * 2);
    const uint32_t pAh = base;
    const uint32_t pAl = base + PARTE * 2;
    const uint32_t pBh = base + 2 * PARTE * 2;
    const uint32_t pBl = base + 3 * PARTE * 2;

    #pragma unroll
    for (int ks = 0; ks < 2; ks++) {
      const int kb = ks * 16;
      uint32_t ah[4][4], al[4][4], bh[4][2], bl[4][2];
      // A frags: ldmatrix x4, rows = m (lane%16), cols = kb + (lane/16)*8
      #pragma unroll
      for (int mt = 0; mt < 4; mt++) {
        int r = wm + mt * 16 + (lane & 15);
        int c = kb + ((lane >> 4) << 3);
        uint32_t off = (uint32_t)(r * AST + c) * 2;
        LDSM4(ah[mt][0], ah[mt][1], ah[mt][2], ah[mt][3], pAh + off);
        LDSM4(al[mt][0], al[mt][1], al[mt][2], al[mt][3], pAl + off);
      }
      // B frags: ldmatrix x4 covers 2 n-tiles (4 8x8 mats)
      #pragma unroll
      for (int p = 0; p < 2; p++) {
        int g = lane >> 3;
        int r = wn + (p * 2 + (g >> 1)) * 8 + (lane & 7);
        int c = kb + ((g & 1) << 3);
        uint32_t off = (uint32_t)(r * AST + c) * 2;
        LDSM4(bh[2 * p][0], bh[2 * p][1], bh[2 * p + 1][0], bh[2 * p + 1][1],
              pBh + off);
        LDSM4(bl[2 * p][0], bl[2 * p][1], bl[2 * p + 1][0], bl[2 * p + 1][1],
              pBl + off);
      }
      // hh + hl + lh passes into the same accumulators
      #pragma unroll
      for (int mt = 0; mt < 4; mt++)
        #pragma unroll
        for (int nt = 0; nt < 4; nt++) mma16816(acc[mt][nt], ah[mt], bh[nt]);
      #pragma unroll
      for (int mt = 0; mt < 4; mt++)
        #pragma unroll
        for (int nt = 0; nt < 4; nt++) mma16816(acc[mt][nt], ah[mt], bl[nt]);
      #pragma unroll
      for (int mt = 0; mt < 4; mt++)
        #pragma unroll
        for (int nt = 0; nt < 4; nt++) mma16816(acc[mt][nt], al[mt], bh[nt]);
    }
    __syncthreads();
  }
  #undef ISSUE

  // epilogue: direct fp32 stores (float2 per row-half)
  #pragma unroll
  for (int mt = 0; mt < 4; mt++) {
    int row = m0 + wm + mt * 16 + (lane >> 2);
    #pragma unroll
    for (int nt = 0; nt < 4; nt++) {
      int col = n0 + wn + nt * 8 + ((lane & 3) << 1);
      *(float2*)&C[(size_t)row * N + col] =
          make_float2(acc[mt][nt][0], acc[mt][nt][1]);
      *(float2*)&C[(size_t)(row + 8) * N + col] =
          make_float2(acc[mt][nt][2], acc[mt][nt][3]);
    }
  }
}

// ---------------- RoPE (neox) in place on q and k of g_qkv ----------------
__global__ __launch_bounds__(256) void rope_kernel(const int* __restrict__ pos) {
  int idx = blockIdx.x * 256 + threadIdx.x;
  int i   = idx & 127;
  int hh  = (idx >> 7) & 31;
  int row = idx >> 12;
  int p = pos[row];
  double inv = exp(((double)(-2.0 * i) / 256.0) * 9.210340371976184);
  double ang = (double)p * inv;
  double sd, cd;
  sincos(ang, &sd, &cd);
  float c = (float)cd, s = (float)sd;
  float* base = g_qkv + (size_t)row * cQKV + hh * cHD;
  float x1 = base[i], x2 = base[i + 128];
  base[i]       = x1 * c - x2 * s;
  base[i + 128] = x2 * c + x1 * s;
}

// ---------------- causal flash attention, fp32 ----------------
constexpr int BQ = 64, BKV = 64;
constexpr int QST = 257;
constexpr int VST = 260;
constexpr int SST = 65;
constexpr int FLASH_SMEM =
    (BQ * QST + BKV * QST + BKV * VST + BQ * SST + 3 * BQ) * 4;

__global__ __launch_bounds__(256) void flash_kernel() {
  extern __shared__ float smf[];
  float* Qs  = smf;
  float* Ks  = Qs + BQ * QST;
  float* Vs  = Ks + BKV * QST;
  float* Ss  = Vs + BKV * VST;
  float* m_s = Ss + BQ * SST;
  float* l_s = m_s + BQ;
  float* f_s = l_s + BQ;

  const int qtile = gridDim.x - 1 - blockIdx.x;
  const int bh = blockIdx.y;
  const int b = bh / cNH, h = bh % cNH;
  const int tid = threadIdx.x;
  const int tx = tid & 15, ty = tid >> 4;
  const int r0 = ty * 4;
  const int c0 = tx * 4;
  const float scale = 0.0625f;

  const float* qb = g_qkv + (size_t)(b * cS + qtile * BQ) * cQKV + h * cHD;
  #pragma unroll
  for (int l = 0; l < 16; l++) {
    int idx = l * 256 + tid;
    int r = idx >> 6, d4 = idx & 63;
    float4 v = *(const float4*)(qb + (size_t)r * cQKV + d4 * 4);
    float* dst = Qs + r * QST + d4 * 4;
    dst[0] = v.x; dst[1] = v.y; dst[2] = v.z; dst[3] = v.w;
  }
  if (tid < BQ) { m_s[tid] = -1e30f; l_s[tid] = 0.0f; }

  float O[4][16];
  #pragma unroll
  for (int i = 0; i < 4; i++)
    #pragma unroll
    for (int j = 0; j < 16; j++) O[i][j] = 0.0f;

  for (int jt = 0; jt <= qtile; jt++) {
    __syncthreads();
    const float* kb = g_qkv + (size_t)(b * cS + jt * BKV) * cQKV + cQSZ + h * cHD;
    const float* vb = kb + cKVSZ;
    #pragma unroll
    for (int l = 0; l < 16; l++) {
      int idx = l * 256 + tid;
      int r = idx >> 6, d4 = idx & 63;
      float4 v = *(const float4*)(kb + (size_t)r * cQKV + d4 * 4);
      float* dst = Ks + r * QST + d4 * 4;
      dst[0] = v.x; dst[1] = v.y; dst[2] = v.z; dst[3] = v.w;
      float4 w = *(const float4*)(vb + (size_t)r * cQKV + d4 * 4);
      *(float4*)(Vs + r * VST + d4 * 4) = w;
    }
    __syncthreads();

    float sc[4][4] = {};
    #pragma unroll 4
    for (int d = 0; d < cHD; d++) {
      float a0 = Qs[(r0 + 0) * QST + d];
      float a1 = Qs[(r0 + 1) * QST + d];
      float a2 = Qs[(r0 + 2) * QST + d];
      float a3 = Qs[(r0 + 3) * QST + d];
      float k0 = Ks[(c0 + 0) * QST + d];
      float k1 = Ks[(c0 + 1) * QST + d];
      float k2 = Ks[(c0 + 2) * QST + d];
      float k3 = Ks[(c0 + 3) * QST + d];
      sc[0][0] += a0 * k0; sc[0][1] += a0 * k1; sc[0][2] += a0 * k2; sc[0][3] += a0 * k3;
      sc[1][0] += a1 * k0; sc[1][1] += a1 * k1; sc[1][2] += a1 * k2; sc[1][3] += a1 * k3;
      sc[2][0] += a2 * k0; sc[2][1] += a2 * k1; sc[2][2] += a2 * k2; sc[2][3] += a2 * k3;
      sc[3][0] += a3 * k0; sc[3][1] += a3 * k1; sc[3][2] += a3 * k2; sc[3][3] += a3 * k3;
    }
    #pragma unroll
    for (int i = 0; i < 4; i++) {
      int qg = qtile * BQ + r0 + i;
      #pragma unroll
      for (int j = 0; j < 4; j++) {
        int kg = jt * BKV + c0 + j;
        Ss[(r0 + i) * SST + c0 + j] = (kg <= qg) ? sc[i][j] * scale : -1e30f;
      }
    }
    __syncthreads();

    {
      int row = tid >> 2, qq = tid & 3;
      float* srow = Ss + row * SST + qq * 16;
      float lm = -1e30f;
      #pragma unroll
      for (int j = 0; j < 16; j++) lm = fmaxf(lm, srow[j]);
      lm = fmaxf(lm, __shfl_xor_sync(0xffffffffu, lm, 1));
      lm = fmaxf(lm, __shfl_xor_sync(0xffffffffu, lm, 2));
      float mold = m_s[row];
      float mnew = fmaxf(mold, lm);
      float sum = 0.0f;
      #pragma unroll
      for (int j = 0; j < 16; j++) {
        float p = expf(srow[j] - mnew);
        srow[j] = p;
        sum += p;
      }
      sum += __shfl_xor_sync(0xffffffffu, sum, 1);
      sum += __shfl_xor_sync(0xffffffffu, sum, 2);
      if (qq == 0) {
        float f = expf(mold - mnew);
        f_s[row] = f;
        m_s[row] = mnew;
        l_s[row] = l_s[row] * f + sum;
      }
    }
    __syncthreads();

    float f0 = f_s[r0], f1 = f_s[r0 + 1], f2 = f_s[r0 + 2], f3 = f_s[r0 + 3];
    #pragma unroll
    for (int i2 = 0; i2 < 16; i2++) {
      O[0][i2] *= f0; O[1][i2] *= f1; O[2][i2] *= f2; O[3][i2] *= f3;
    }
    for (int kk = 0; kk < BKV; kk++) {
      float p0 = Ss[(r0 + 0) * SST + kk];
      float p1 = Ss[(r0 + 1) * SST + kk];
      float p2 = Ss[(r0 + 2) * SST + kk];
      float p3 = Ss[(r0 + 3) * SST + kk];
      const float* vr = Vs + kk * VST + tx;
      #pragma unroll
      for (int i2 = 0; i2 < 16; i2++) {
        float v = vr[i2 * 16];
        O[0][i2] += p0 * v;
        O[1][i2] += p1 * v;
        O[2][i2] += p2 * v;
        O[3][i2] += p3 * v;
      }
    }
  }

  float* ob = g_attn + (size_t)(b * cS + qtile * BQ) * cQSZ + h * cHD;
  #pragma unroll
  for (int i = 0; i < 4; i++) {
    float rl = 1.0f / l_s[r0 + i];
    #pragma unroll
    for (int i2 = 0; i2 < 16; i2++) {
      ob[(size_t)(r0 + i) * cQSZ + tx + 16 * i2] = O[i][i2] * rl;
    }
  }
}

// ---------------- launch ----------------
extern "C" void kernel_launch(void* const* d_in, const int* in_sizes, int n_in,
                              void* d_out, int out_size) {
  (void)in_sizes; (void)n_in; (void)out_size;
  const float* hidden = (const float*)d_in[0];
  const int*   pos    = (const int*)d_in[1];
  const float* Wqkv   = (const float*)d_in[2];
  const float* Wo     = (const float*)d_in[3];
  float* out = (float*)d_out;

  float *qkv_p, *attn_p;
  __nv_bfloat16 *hidh, *hidl, *w1h, *w1l, *ath, *atl, *w2h, *w2l;
  cudaGetSymbolAddress((void**)&qkv_p, g_qkv);
  cudaGetSymbolAddress((void**)&attn_p, g_attn);
  cudaGetSymbolAddress((void**)&hidh, g_hid_h);
  cudaGetSymbolAddress((void**)&hidl, g_hid_l);
  cudaGetSymbolAddress((void**)&w1h, g_w1_h);
  cudaGetSymbolAddress((void**)&w1l, g_w1_l);
  cudaGetSymbolAddress((void**)&ath, g_at_h);
  cudaGetSymbolAddress((void**)&atl, g_at_l);
  cudaGetSymbolAddress((void**)&w2h, g_w2_h);
  cudaGetSymbolAddress((void**)&w2l, g_w2_l);

  cudaFuncSetAttribute(flash_kernel,
                       cudaFuncAttributeMaxDynamicSharedMemorySize, FLASH_SMEM);
  cudaFuncSetAttribute(gemm_hmma,
                       cudaFuncAttributeMaxDynamicSharedMemorySize, HG_SMEM);

  // 1) split hidden, transpose+split Wqkv
  {
    int n4 = cM * cH / 4;
    split_kernel<<<(n4 + 255) / 256, 256>>>(hidden, hidh, hidl, n4);
    tsplit_kernel<<<dim3(cQKV / 32, cH / 32), 256>>>(Wqkv, w1h, w1l, cH, cQKV);
  }
  // 2) QKV projection (HMMA): [4096,3072] x [3072,12288]
  gemm_hmma<<<dim3(cQKV / BN, cM / BM), 256, HG_SMEM>>>(
      hidh, hidl, w1h, w1l, qkv_p, cM, cQKV, cH);
  // 3) RoPE
  rope_kernel<<<(cM * 32 * 128) / 256, 256>>>(pos);
  // 4) flash attention
  flash_kernel<<<dim3(cS / BQ, cB * cNH), 256, FLASH_SMEM>>>();
  // 5) split attn, transpose+split Wo
  {
    int n4 = cM * cQSZ / 4;
    split_kernel<<<(n4 + 255) / 256, 256>>>(attn_p, ath, atl, n4);
    tsplit_kernel<<<dim3(cH / 32, cQSZ / 32), 256>>>(Wo, w2h, w2l, cQSZ, cH);
  }
  // 6) output projection (HMMA): [4096,4096] x [4096,3072]
  gemm_hmma<<<dim3(cH / BN, cM / BM), 256, HG_SMEM>>>(
      ath, atl, w2h, w2l, out, cM, cH, cQSZ);
}

// round 4
// speedup vs baseline: 2.9640x; 1.7297x over previous
#include <cuda_runtime.h>
#include <cuda_bf16.h>
#include <math.h>
#include <stdint.h>

// ---------------- problem constants ----------------
namespace {
constexpr int cB  = 2;
constexpr int cS  = 2048;
constexpr int cH  = 3072;
constexpr int cNH = 16;
constexpr int cHD = 256;
constexpr int cQSZ  = cNH * cHD;            // 4096
constexpr int cKVSZ = cQSZ;                 // 4096
constexpr int cQKV  = cQSZ + 2 * cKVSZ;     // 12288
constexpr int cM    = cB * cS;              // 4096 rows
}

// ---------------- scratch ----------------
__device__ float g_qkv[(size_t)cM * cQKV];
__device__ __nv_bfloat16 g_hid_h[(size_t)cM * cH];
__device__ __nv_bfloat16 g_hid_l[(size_t)cM * cH];
__device__ __nv_bfloat16 g_w1_h[(size_t)cQKV * cH];
__device__ __nv_bfloat16 g_w1_l[(size_t)cQKV * cH];
__device__ __nv_bfloat16 g_at_h[(size_t)cM * cQSZ];
__device__ __nv_bfloat16 g_at_l[(size_t)cM * cQSZ];
__device__ __nv_bfloat16 g_w2_h[(size_t)cH * cQSZ];
__device__ __nv_bfloat16 g_w2_l[(size_t)cH * cQSZ];
// head-major [bh][s][d] bf16 hi/lo for attention
__device__ __nv_bfloat16 g_qh[(size_t)cM * cQSZ];
__device__ __nv_bfloat16 g_ql[(size_t)cM * cQSZ];
__device__ __nv_bfloat16 g_kh[(size_t)cM * cQSZ];
__device__ __nv_bfloat16 g_kl[(size_t)cM * cQSZ];
__device__ __nv_bfloat16 g_vh[(size_t)cM * cQSZ];
__device__ __nv_bfloat16 g_vl[(size_t)cM * cQSZ];
__device__ double g_invf[128];

// ---------------- helpers (base ISA, compute_103-safe) ----------------
__device__ __forceinline__ uint32_t smem_u32(const void* p) {
  uint32_t a;
  asm("{ .reg .u64 t; cvta.to.shared.u64 t, %1; cvt.u32.u64 %0, t; }"
      : "=r"(a) : "l"(p));
  return a;
}
#define CP_ASYNC16(dst, src) \
  asm volatile("cp.async.cg.shared.global [%0], [%1], 16;" :: "r"(dst), "l"(src))
#define CP_COMMIT() asm volatile("cp.async.commit_group;" ::: "memory")
#define CP_WAIT(n)  asm volatile("cp.async.wait_group %0;" :: "n"(n) : "memory")
#define LDSM4(r0, r1, r2, r3, addr) \
  asm volatile("ldmatrix.sync.aligned.m8n8.x4.shared.b16 {%0,%1,%2,%3}, [%4];" \
               : "=r"(r0), "=r"(r1), "=r"(r2), "=r"(r3) : "r"(addr))
#define LDSM4T(r0, r1, r2, r3, addr) \
  asm volatile("ldmatrix.sync.aligned.m8n8.x4.trans.shared.b16 {%0,%1,%2,%3}, [%4];" \
               : "=r"(r0), "=r"(r1), "=r"(r2), "=r"(r3) : "r"(addr))

__device__ __forceinline__ void mma16816(float* d, const uint32_t* a,
                                         const uint32_t* b) {
  asm volatile(
      "mma.sync.aligned.m16n8k16.row.col.f32.bf16.bf16.f32 "
      "{%0,%1,%2,%3}, {%4,%5,%6,%7}, {%8,%9}, {%0,%1,%2,%3};"
      : "+f"(d[0]), "+f"(d[1]), "+f"(d[2]), "+f"(d[3])
      : "r"(a[0]), "r"(a[1]), "r"(a[2]), "r"(a[3]), "r"(b[0]), "r"(b[1]));
}

// ---------------- split fp32 -> bf16 hi/lo ----------------
__global__ __launch_bounds__(256) void split_kernel(
    const float* __restrict__ x, __nv_bfloat16* __restrict__ h,
    __nv_bfloat16* __restrict__ l, int n4) {
  int i = blockIdx.x * 256 + threadIdx.x;
  if (i >= n4) return;
  float4 v = ((const float4*)x)[i];
  float vv[4] = {v.x, v.y, v.z, v.w};
  __nv_bfloat16 hh[4], ll[4];
  #pragma unroll
  for (int q = 0; q < 4; q++) {
    hh[q] = __float2bfloat16(vv[q]);
    ll[q] = __float2bfloat16(vv[q] - __bfloat162float(hh[q]));
  }
  ((__nv_bfloat162*)h)[2 * i]     = __nv_bfloat162(hh[0], hh[1]);
  ((__nv_bfloat162*)h)[2 * i + 1] = __nv_bfloat162(hh[2], hh[3]);
  ((__nv_bfloat162*)l)[2 * i]     = __nv_bfloat162(ll[0], ll[1]);
  ((__nv_bfloat162*)l)[2 * i + 1] = __nv_bfloat162(ll[2], ll[3]);
}

// ---------------- transpose + split ----------------
__global__ __launch_bounds__(256) void tsplit_kernel(
    const float* __restrict__ W, __nv_bfloat16* __restrict__ Th,
    __nv_bfloat16* __restrict__ Tl, int K, int N) {
  __shared__ float sm[32][33];
  int n0 = blockIdx.x * 32, k0 = blockIdx.y * 32;
  int tx = threadIdx.x & 31, ty = threadIdx.x >> 5;
  #pragma unroll
  for (int q = 0; q < 4; q++)
    sm[ty + 8 * q][tx] = W[(size_t)(k0 + ty + 8 * q) * N + n0 + tx];
  __syncthreads();
  #pragma unroll
  for (int q = 0; q < 4; q++) {
    float x = sm[tx][ty + 8 * q];
    __nv_bfloat16 h = __float2bfloat16(x);
    float lo = x - __bfloat162float(h);
    size_t o = (size_t)(n0 + ty + 8 * q) * K + k0 + tx;
    Th[o] = h;
    Tl[o] = __float2bfloat16(lo);
  }
}

// ---------------- HMMA GEMM (unchanged from R3) ----------------
constexpr int BM = 128, BN = 128, BKt = 32;
constexpr int AST = 40;
constexpr int PARTE = 128 * AST;
constexpr int BUFE  = 4 * PARTE;
constexpr int HG_SMEM = 2 * BUFE * 2;

__global__ __launch_bounds__(256, 2) void gemm_hmma(
    const __nv_bfloat16* __restrict__ Ah, const __nv_bfloat16* __restrict__ Al,
    const __nv_bfloat16* __restrict__ Bh, const __nv_bfloat16* __restrict__ Bl,
    float* __restrict__ C, int M, int N, int K) {
  extern __shared__ __nv_bfloat16 smb[];
  const uint32_t sbase = smem_u32(smb);
  const int tid = threadIdx.x, lane = tid & 31, wid = tid >> 5;
  const int m0 = blockIdx.y * BM, n0 = blockIdx.x * BN;
  const int wm = (wid & 1) * 64, wn = (wid >> 1) * 32;

  float acc[4][4][4];
  #pragma unroll
  for (int i = 0; i < 4; i++)
    #pragma unroll
    for (int j = 0; j < 4; j++)
      #pragma unroll
      for (int q = 0; q < 4; q++) acc[i][j][q] = 0.0f;

  const int T = K / BKt;
  int ldr[2], ldc[2];
  #pragma unroll
  for (int i = 0; i < 2; i++) {
    int idx = tid + i * 256;
    ldr[i] = idx >> 2;
    ldc[i] = idx & 3;
  }

  #define ISSUE(t)                                                          \
    do {                                                                    \
      int k0_ = (t) * BKt;                                                  \
      uint32_t db_ = sbase + ((t) & 1) * (BUFE * 2);                        \
      _Pragma("unroll")                                                     \
      for (int i_ = 0; i_ < 2; i_++) {                                      \
        int r_ = ldr[i_], c_ = ldc[i_];                                     \
        size_t ao_ = (size_t)(m0 + r_) * K + k0_ + c_ * 8;                  \
        size_t bo_ = (size_t)(n0 + r_) * K + k0_ + c_ * 8;                  \
        uint32_t d_ = db_ + (r_ * AST + c_ * 8) * 2;                        \
        CP_ASYNC16(d_, Ah + ao_);                                           \
        CP_ASYNC16(d_ + PARTE * 2, Al + ao_);                               \
        CP_ASYNC16(d_ + 2 * PARTE * 2, Bh + bo_);                           \
        CP_ASYNC16(d_ + 3 * PARTE * 2, Bl + bo_);                           \
      }                                                                     \
    } while (0)

  ISSUE(0);
  CP_COMMIT();

  for (int t = 0; t < T; t++) {
    if (t + 1 < T) {
      ISSUE(t + 1);
      CP_COMMIT();
      CP_WAIT(1);
    } else {
      CP_WAIT(0);
    }
    __syncthreads();

    uint32_t base = sbase + (t & 1) * (BUFE * 2);
    const uint32_t pAh = base;
    const uint32_t pAl = base + PARTE * 2;
    const uint32_t pBh = base + 2 * PARTE * 2;
    const uint32_t pBl = base + 3 * PARTE * 2;

    #pragma unroll
    for (int ks = 0; ks < 2; ks++) {
      const int kb = ks * 16;
      uint32_t ah[4][4], al[4][4], bh[4][2], bl[4][2];
      #pragma unroll
      for (int mt = 0; mt < 4; mt++) {
        int r = wm + mt * 16 + (lane & 15);
        int c = kb + ((lane >> 4) << 3);
        uint32_t off = (uint32_t)(r * AST + c) * 2;
        LDSM4(ah[mt][0], ah[mt][1], ah[mt][2], ah[mt][3], pAh + off);
        LDSM4(al[mt][0], al[mt][1], al[mt][2], al[mt][3], pAl + off);
      }
      #pragma unroll
      for (int p = 0; p < 2; p++) {
        int g = lane >> 3;
        int r = wn + (p * 2 + (g >> 1)) * 8 + (lane & 7);
        int c = kb + ((g & 1) << 3);
        uint32_t off = (uint32_t)(r * AST + c) * 2;
        LDSM4(bh[2 * p][0], bh[2 * p][1], bh[2 * p + 1][0], bh[2 * p + 1][1],
              pBh + off);
        LDSM4(bl[2 * p][0], bl[2 * p][1], bl[2 * p + 1][0], bl[2 * p + 1][1],
              pBl + off);
      }
      #pragma unroll
      for (int mt = 0; mt < 4; mt++)
        #pragma unroll
        for (int nt = 0; nt < 4; nt++) mma16816(acc[mt][nt], ah[mt], bh[nt]);
      #pragma unroll
      for (int mt = 0; mt < 4; mt++)
        #pragma unroll
        for (int nt = 0; nt < 4; nt++) mma16816(acc[mt][nt], ah[mt], bl[nt]);
      #pragma unroll
      for (int mt = 0; mt < 4; mt++)
        #pragma unroll
        for (int nt = 0; nt < 4; nt++) mma16816(acc[mt][nt], al[mt], bh[nt]);
    }
    __syncthreads();
  }
  #undef ISSUE

  #pragma unroll
  for (int mt = 0; mt < 4; mt++) {
    int row = m0 + wm + mt * 16 + (lane >> 2);
    #pragma unroll
    for (int nt = 0; nt < 4; nt++) {
      int col = n0 + wn + nt * 8 + ((lane & 3) << 1);
      *(float2*)&C[(size_t)row * N + col] =
          make_float2(acc[mt][nt][0], acc[mt][nt][1]);
      *(float2*)&C[(size_t)(row + 8) * N + col] =
          make_float2(acc[mt][nt][2], acc[mt][nt][3]);
    }
  }
}

// ---------------- inv_freq table (double, once) ----------------
__global__ void invf_init() {
  int i = threadIdx.x;
  if (i < 128)
    g_invf[i] = exp(((double)(-2.0 * i) / 256.0) * 9.210340371976184);
}

// ---------------- RoPE: fp32 qkv -> head-major bf16 hi/lo (q scaled) ------
__global__ __launch_bounds__(256) void rope_kernel(const int* __restrict__ pos) {
  int idx = blockIdx.x * 256 + threadIdx.x;   // cM*32*128 threads
  int i   = idx & 127;
  int hh  = (idx >> 7) & 31;                  // 0-15 q heads, 16-31 k heads
  int row = idx >> 12;
  int p = pos[row];
  double ang = (double)p * g_invf[i];
  const double INV2PI = 0.15915494309189535;
  const double TWOPI  = 6.283185307179586;
  int kk = __double2int_rn(ang * INV2PI);
  float fr = (float)(ang - TWOPI * (double)kk);
  float s, c;
  __sincosf(fr, &s, &c);
  const float* base = g_qkv + (size_t)row * cQKV + hh * cHD;
  float x1 = base[i], x2 = base[i + 128];
  float y1 = x1 * c - x2 * s;
  float y2 = x2 * c + x1 * s;
  int b = row >> 11, sidx = row & 2047;
  bool isq = hh < 16;
  int head = isq ? hh : hh - 16;
  if (isq) { y1 *= 0.0625f; y2 *= 0.0625f; }   // fold softmax scale into Q
  size_t o = ((size_t)(b * cNH + head) * cS + sidx) * cHD + i;
  __nv_bfloat16* dh = isq ? g_qh : g_kh;
  __nv_bfloat16* dl = isq ? g_ql : g_kl;
  __nv_bfloat16 h1 = __float2bfloat16(y1);
  __nv_bfloat16 h2 = __float2bfloat16(y2);
  dh[o]       = h1;
  dh[o + 128] = h2;
  dl[o]       = __float2bfloat16(y1 - __bfloat162float(h1));
  dl[o + 128] = __float2bfloat16(y2 - __bfloat162float(h2));
}

// ---------------- V split: fp32 qkv v-part -> head-major bf16 hi/lo -------
__global__ __launch_bounds__(256) void vsplit_kernel() {
  int idx = blockIdx.x * 256 + threadIdx.x;   // cM*4096/4 threads
  int d4 = idx & 63;                          // float4 within head dim
  int h  = (idx >> 6) & 15;
  int row = idx >> 10;
  int b = row >> 11, sidx = row & 2047;
  float4 v = *(const float4*)(g_qkv + (size_t)row * cQKV + 2 * cQSZ + h * cHD +
                              d4 * 4);
  float vv[4] = {v.x, v.y, v.z, v.w};
  size_t o = ((size_t)(b * cNH + h) * cS + sidx) * cHD + d4 * 4;
  __nv_bfloat16 hh[4], ll[4];
  #pragma unroll
  for (int q = 0; q < 4; q++) {
    hh[q] = __float2bfloat16(vv[q]);
    ll[q] = __float2bfloat16(vv[q] - __bfloat162float(hh[q]));
  }
  *(__nv_bfloat162*)(g_vh + o)     = __nv_bfloat162(hh[0], hh[1]);
  *(__nv_bfloat162*)(g_vh + o + 2) = __nv_bfloat162(hh[2], hh[3]);
  *(__nv_bfloat162*)(g_vl + o)     = __nv_bfloat162(ll[0], ll[1]);
  *(__nv_bfloat162*)(g_vl + o + 2) = __nv_bfloat162(ll[2], ll[3]);
}

// ---------------- HMMA flash attention ----------------
// BQ=64, BKV=64, HD=256. 8 warps = 4 row-groups x 2 halves.
constexpr int FQST = 264;              // q/k/v smem row stride (bf16)
constexpr int FPST = 72;               // P smem row stride
constexpr int F_QH = 0;
constexpr int F_QL = 64 * FQST;
constexpr int F_KH = 2 * 64 * FQST;
constexpr int F_KL = 3 * 64 * FQST;
constexpr int F_VH = 4 * 64 * FQST;
constexpr int F_VL = 5 * 64 * FQST;
constexpr int F_PH = 6 * 64 * FQST;
constexpr int F_PL = F_PH + 64 * FPST;
constexpr int F_TOT = F_PL + 64 * FPST;            // bf16 elems
constexpr int FLASH_SMEM = F_TOT * 2 + 448 * 4;    // + float reductions

__global__ __launch_bounds__(256, 1) void flash_hmma(
    __nv_bfloat16* __restrict__ ath, __nv_bfloat16* __restrict__ atl) {
  extern __shared__ __nv_bfloat16 smem[];
  const uint32_t sb = smem_u32(smem);
  float* fre  = (float*)(smem + F_TOT);
  float* m_s  = fre;
  float* l_s  = fre + 64;
  float* f_s  = fre + 128;
  float* rmax = fre + 192;   // [2][64]
  float* rsum = fre + 320;   // [2][64]

  const int qtile = gridDim.x - 1 - blockIdx.x;  // heavy tiles first
  const int bh = blockIdx.y;
  const int b = bh >> 4, h = bh & 15;
  const int tid = threadIdx.x, lane = tid & 31, wid = tid >> 5;
  const int wm = wid & 3, wg = wid >> 2;
  const int q0 = qtile * 64;

  const __nv_bfloat16* qhb = g_qh + ((size_t)bh * cS + q0) * cHD;
  const __nv_bfloat16* qlb = g_ql + ((size_t)bh * cS + q0) * cHD;
  const __nv_bfloat16* khb = g_kh + (size_t)bh * cS * cHD;
  const __nv_bfloat16* klb = g_kl + (size_t)bh * cS * cHD;
  const __nv_bfloat16* vhb = g_vh + (size_t)bh * cS * cHD;
  const __nv_bfloat16* vlb = g_vl + (size_t)bh * cS * cHD;

  #define LOADP(gptr, soff)                                              \
    do {                                                                 \
      _Pragma("unroll")                                                  \
      for (int i_ = 0; i_ < 8; i_++) {                                   \
        int id_ = tid + 256 * i_;                                        \
        int r_ = id_ >> 5, c_ = id_ & 31;                                \
        CP_ASYNC16(sb + (uint32_t)((soff) + r_ * FQST + c_ * 8) * 2,     \
                   (gptr) + r_ * 256 + c_ * 8);                          \
      }                                                                  \
    } while (0)

  // preload Q + K(0) as group 1, V(0) as group 2
  LOADP(qhb, F_QH);
  LOADP(qlb, F_QL);
  LOADP(khb, F_KH);
  LOADP(klb, F_KL);
  CP_COMMIT();
  LOADP(vhb, F_VH);
  LOADP(vlb, F_VL);
  CP_COMMIT();

  if (tid < 64) { m_s[tid] = -1e30f; l_s[tid] = 0.0f; }

  float o[16][4];
  #pragma unroll
  for (int i = 0; i < 16; i++)
    #pragma unroll
    for (int j = 0; j < 4; j++) o[i][j] = 0.0f;

  const uint32_t pQh = sb + F_QH * 2, pQl = sb + F_QL * 2;
  const uint32_t pKh = sb + F_KH * 2, pKl = sb + F_KL * 2;
  const uint32_t pVh = sb + F_VH * 2, pVl = sb + F_VL * 2;
  const uint32_t pPh = sb + F_PH * 2, pPl = sb + F_PL * 2;

  const int arow = 16 * wm + (lane & 15);          // A-frag row
  const int acol = (lane >> 4) * 8;                // A-frag col-half
  const int brow = wg * 32 + (lane & 7) + (lane >> 4) * 8;  // K b-frag row
  const int bcol = ((lane >> 3) & 1) * 8;                   // K b-frag k-half
  const int row0 = 16 * wm + (lane >> 2);

  for (int jt = 0; jt <= qtile; jt++) {
    CP_WAIT(1);
    __syncthreads();   // Q(+first K) / K(jt) in smem

    // ---- S = Q K^T (3 hi/lo passes) ----
    float s[4][4];
    #pragma unroll
    for (int nt = 0; nt < 4; nt++)
      #pragma unroll
      for (int c = 0; c < 4; c++) s[nt][c] = 0.0f;

    #pragma unroll 4
    for (int ks = 0; ks < 16; ks++) {
      const int k0 = ks * 16;
      uint32_t aoff = (uint32_t)(arow * FQST + k0 + acol) * 2;
      uint32_t aqh[4], aql[4], bkh0[4], bkh1[4], bkl0[4], bkl1[4];
      LDSM4(aqh[0], aqh[1], aqh[2], aqh[3], pQh + aoff);
      LDSM4(aql[0], aql[1], aql[2], aql[3], pQl + aoff);
      uint32_t boff0 = (uint32_t)(brow * FQST + k0 + bcol) * 2;
      uint32_t boff1 = boff0 + 16 * FQST * 2;
      LDSM4(bkh0[0], bkh0[1], bkh0[2], bkh0[3], pKh + boff0);
      LDSM4(bkh1[0], bkh1[1], bkh1[2], bkh1[3], pKh + boff1);
      LDSM4(bkl0[0], bkl0[1], bkl0[2], bkl0[3], pKl + boff0);
      LDSM4(bkl1[0], bkl1[1], bkl1[2], bkl1[3], pKl + boff1);
      uint32_t* bh[4] = {&bkh0[0], &bkh0[2], &bkh1[0], &bkh1[2]};
      uint32_t* bl[4] = {&bkl0[0], &bkl0[2], &bkl1[0], &bkl1[2]};
      #pragma unroll
      for (int nt = 0; nt < 4; nt++) mma16816(s[nt], aqh, bh[nt]);
      #pragma unroll
      for (int nt = 0; nt < 4; nt++) mma16816(s[nt], aqh, bl[nt]);
      #pragma unroll
      for (int nt = 0; nt < 4; nt++) mma16816(s[nt], aql, bh[nt]);
    }

    // ---- causal mask (diagonal tile only) ----
    if (jt == qtile) {
      #pragma unroll
      for (int nt = 0; nt < 4; nt++)
        #pragma unroll
        for (int c = 0; c < 4; c++) {
          int kvloc = wg * 32 + nt * 8 + (lane & 3) * 2 + (c & 1);
          int qloc = 16 * wm + (lane >> 2) + 8 * (c >> 1);
          if (kvloc > qloc) s[nt][c] = -1e30f;
        }
    }

    // ---- row max (quad + cross-warp) ----
    float lm0 = -1e30f, lm1 = -1e30f;
    #pragma unroll
    for (int nt = 0; nt < 4; nt++) {
      lm0 = fmaxf(lm0, fmaxf(s[nt][0], s[nt][1]));
      lm1 = fmaxf(lm1, fmaxf(s[nt][2], s[nt][3]));
    }
    lm0 = fmaxf(lm0, __shfl_xor_sync(0xffffffffu, lm0, 1));
    lm0 = fmaxf(lm0, __shfl_xor_sync(0xffffffffu, lm0, 2));
    lm1 = fmaxf(lm1, __shfl_xor_sync(0xffffffffu, lm1, 1));
    lm1 = fmaxf(lm1, __shfl_xor_sync(0xffffffffu, lm1, 2));
    if ((lane & 3) == 0) {
      rmax[wg * 64 + row0] = lm0;
      rmax[wg * 64 + row0 + 8] = lm1;
    }
    __syncthreads();
    if (tid < 64) {
      float mo = m_s[tid];
      float mn = fmaxf(mo, fmaxf(rmax[tid], rmax[64 + tid]));
      f_s[tid] = __expf(mo - mn);
      m_s[tid] = mn;
    }
    __syncthreads();

    // ---- exp, P store (bf16 hi/lo), O rescale, row sums ----
    {
      float mn0 = m_s[row0], mn1 = m_s[row0 + 8];
      float sum0 = 0.0f, sum1 = 0.0f;
      #pragma unroll
      for (int nt = 0; nt < 4; nt++) {
        float p0 = __expf(s[nt][0] - mn0);
        float p1 = __expf(s[nt][1] - mn0);
        float p2 = __expf(s[nt][2] - mn1);
        float p3 = __expf(s[nt][3] - mn1);
        sum0 += p0 + p1;
        sum1 += p2 + p3;
        __nv_bfloat16 h0 = __float2bfloat16(p0), h1 = __float2bfloat16(p1);
        __nv_bfloat16 h2 = __float2bfloat16(p2), h3 = __float2bfloat16(p3);
        int col = wg * 32 + nt * 8 + (lane & 3) * 2;
        *(__nv_bfloat162*)(smem + F_PH + row0 * FPST + col) =
            __nv_bfloat162(h0, h1);
        *(__nv_bfloat162*)(smem + F_PH + (row0 + 8) * FPST + col) =
            __nv_bfloat162(h2, h3);
        *(__nv_bfloat162*)(smem + F_PL + row0 * FPST + col) =
            __nv_bfloat162(__float2bfloat16(p0 - __bfloat162float(h0)),
                           __float2bfloat16(p1 - __bfloat162float(h1)));
        *(__nv_bfloat162*)(smem + F_PL + (row0 + 8) * FPST + col) =
            __nv_bfloat162(__float2bfloat16(p2 - __bfloat162float(h2)),
                           __float2bfloat16(p3 - __bfloat162float(h3)));
      }
      sum0 += __shfl_xor_sync(0xffffffffu, sum0, 1);
      sum0 += __shfl_xor_sync(0xffffffffu, sum0, 2);
      sum1 += __shfl_xor_sync(0xffffffffu, sum1, 1);
      sum1 += __shfl_xor_sync(0xffffffffu, sum1, 2);
      if ((lane & 3) == 0) {
        rsum[wg * 64 + row0] = sum0;
        rsum[wg * 64 + row0 + 8] = sum1;
      }
      float f0 = f_s[row0], f1 = f_s[row0 + 8];
      #pragma unroll
      for (int dt = 0; dt < 16; dt++) {
        o[dt][0] *= f0; o[dt][1] *= f0;
        o[dt][2] *= f1; o[dt][3] *= f1;
      }
    }

    CP_WAIT(0);          // V(jt) arrived
    __syncthreads();     // P visible, K consumed

    if (jt < qtile) {    // prefetch next K while PV runs
      LOADP(khb + (jt + 1) * 64 * 256, F_KH);
      LOADP(klb + (jt + 1) * 64 * 256, F_KL);
      CP_COMMIT();
    }
    if (tid < 64) l_s[tid] = l_s[tid] * f_s[tid] + rsum[tid] + rsum[64 + tid];

    // ---- O += P V (3 hi/lo passes) ----
    #pragma unroll
    for (int ks = 0; ks < 4; ks++) {
      const int k0 = ks * 16;
      uint32_t aph[4], apl[4];
      uint32_t paoff = (uint32_t)(arow * FPST + k0 + acol) * 2;
      LDSM4(aph[0], aph[1], aph[2], aph[3], pPh + paoff);
      LDSM4(apl[0], apl[1], apl[2], apl[3], pPl + paoff);
      const int vrow = k0 + (lane & 15);
      #pragma unroll
      for (int dt2 = 0; dt2 < 8; dt2++) {
        int dbase = wg * 128 + dt2 * 16 + (lane >> 4) * 8;
        uint32_t voff = (uint32_t)(vrow * FQST + dbase) * 2;
        uint32_t bvh[4], bvl[4];
        LDSM4T(bvh[0], bvh[1], bvh[2], bvh[3], pVh + voff);
        LDSM4T(bvl[0], bvl[1], bvl[2], bvl[3], pVl + voff);
        mma16816(o[dt2 * 2], aph, &bvh[0]);
        mma16816(o[dt2 * 2], aph, &bvl[0]);
        mma16816(o[dt2 * 2], apl, &bvh[0]);
        mma16816(o[dt2 * 2 + 1], aph, &bvh[2]);
        mma16816(o[dt2 * 2 + 1], aph, &bvl[2]);
        mma16816(o[dt2 * 2 + 1], apl, &bvh[2]);
      }
    }
    __syncthreads();     // V consumed
    if (jt < qtile) {
      LOADP(vhb + (jt + 1) * 64 * 256, F_VH);
      LOADP(vlb + (jt + 1) * 64 * 256, F_VL);
      CP_COMMIT();
    }
  }
  #undef LOADP

  // ---- epilogue: /l, write bf16 hi/lo to [b,s,h*256+d] ----
  float rl0 = 1.0f / l_s[row0];
  float rl1 = 1.0f / l_s[row0 + 8];
  size_t g0 = ((size_t)(b * cS + q0 + row0)) * cQSZ + h * cHD;
  size_t g1 = g0 + 8 * cQSZ;
  #pragma unroll
  for (int dt = 0; dt < 16; dt++) {
    int col = wg * 128 + dt * 8 + (lane & 3) * 2;
    float v0 = o[dt][0] * rl0, v1 = o[dt][1] * rl0;
    float v2 = o[dt][2] * rl1, v3 = o[dt][3] * rl1;
    __nv_bfloat16 h0 = __float2bfloat16(v0), h1 = __float2bfloat16(v1);
    __nv_bfloat16 h2 = __float2bfloat16(v2), h3 = __float2bfloat16(v3);
    *(__nv_bfloat162*)(ath + g0 + col) = __nv_bfloat162(h0, h1);
    *(__nv_bfloat162*)(ath + g1 + col) = __nv_bfloat162(h2, h3);
    *(__nv_bfloat162*)(atl + g0 + col) =
        __nv_bfloat162(__float2bfloat16(v0 - __bfloat162float(h0)),
                       __float2bfloat16(v1 - __bfloat162float(h1)));
    *(__nv_bfloat162*)(atl + g1 + col) =
        __nv_bfloat162(__float2bfloat16(v2 - __bfloat162float(h2)),
                       __float2bfloat16(v3 - __bfloat162float(h3)));
  }
}

// ---------------- launch ----------------
extern "C" void kernel_launch(void* const* d_in, const int* in_sizes, int n_in,
                              void* d_out, int out_size) {
  (void)in_sizes; (void)n_in; (void)out_size;
  const float* hidden = (const float*)d_in[0];
  const int*   pos    = (const int*)d_in[1];
  const float* Wqkv   = (const float*)d_in[2];
  const float* Wo     = (const float*)d_in[3];
  float* out = (float*)d_out;

  float* qkv_p;
  __nv_bfloat16 *hidh, *hidl, *w1h, *w1l, *ath, *atl, *w2h, *w2l;
  cudaGetSymbolAddress((void**)&qkv_p, g_qkv);
  cudaGetSymbolAddress((void**)&hidh, g_hid_h);
  cudaGetSymbolAddress((void**)&hidl, g_hid_l);
  cudaGetSymbolAddress((void**)&w1h, g_w1_h);
  cudaGetSymbolAddress((void**)&w1l, g_w1_l);
  cudaGetSymbolAddress((void**)&ath, g_at_h);
  cudaGetSymbolAddress((void**)&atl, g_at_l);
  cudaGetSymbolAddress((void**)&w2h, g_w2_h);
  cudaGetSymbolAddress((void**)&w2l, g_w2_l);

  cudaFuncSetAttribute(gemm_hmma,
                       cudaFuncAttributeMaxDynamicSharedMemorySize, HG_SMEM);
  cudaFuncSetAttribute(flash_hmma,
                       cudaFuncAttributeMaxDynamicSharedMemorySize, FLASH_SMEM);

  invf_init<<<1, 128>>>();
  {
    int n4 = cM * cH / 4;
    split_kernel<<<(n4 + 255) / 256, 256>>>(hidden, hidh, hidl, n4);
    tsplit_kernel<<<dim3(cQKV / 32, cH / 32), 256>>>(Wqkv, w1h, w1l, cH, cQKV);
    tsplit_kernel<<<dim3(cH / 32, cQSZ / 32), 256>>>(Wo, w2h, w2l, cQSZ, cH);
  }
  // QKV projection
  gemm_hmma<<<dim3(cQKV / BN, cM / BM), 256, HG_SMEM>>>(
      hidh, hidl, w1h, w1l, qkv_p, cM, cQKV, cH);
  // RoPE (-> head-major bf16 hi/lo, scaled Q) and V split
  rope_kernel<<<(cM * 32 * 128) / 256, 256>>>(pos);
  vsplit_kernel<<<(cM * cQSZ / 4) / 256, 256>>>();
  // flash attention (HMMA)
  flash_hmma<<<dim3(cS / 64, cB * cNH), 256, FLASH_SMEM>>>(ath, atl);
  // output projection
  gemm_hmma<<<dim3(cH / BN, cM / BM), 256, HG_SMEM>>>(
      ath, atl, w2h, w2l, out, cM, cH, cQSZ);
}